// round 7
// baseline (speedup 1.0000x reference)
#include <cuda_runtime.h>

// ---------------------------------------------------------------------------
// MultitaskSNN round 7: 2 batch elements per thread + output-neuron-pair
// f32x2 packing. Key idea: each weight-pair {w[n],w[n+1]} is loaded from SMEM
// ONCE and used for BOTH batch elements -> SMEM crossbar weight traffic is
// halved vs rounds 3-6 (which were pinned at the per-lane replication wall).
// Layer-1 spikes are compressed to 28-bit masks to cap register pressure.
// Per-neuron arithmetic (ascending-i FMA chain, bias after sum,
// fma(0.9,m,cur)-reset) is unchanged -> bit-exact vs reference.
// ---------------------------------------------------------------------------

typedef unsigned long long u64;
typedef unsigned int u32;

#define TT 50
#define NIN 32
#define THREADS 64

// u64-unit smem offsets (even -> 16B aligned)
#define U_W1   0      // [i=32][p=14] layer-1 weight pairs (448)
#define U_B1   448    // 14 bias pairs
#define U_W24  462    // [i=28][p=12] fused L2(4)+L4(7)+pad (336)
#define U_B24  798    // 12 bias pairs (11 used)
#define U_W3   810    // [i=8][p=2] class-out pairs (16)
#define U_B3   826    // 2 bias pairs
#define U_END  828
// float-unit offsets
#define F_W5   1656   // 14 reg-out weights (16B aligned)
#define F_B5   1670
#define SW_FLOATS 1672

__device__ __forceinline__ u64 pack2(float lo, float hi) {
    u64 r; asm("mov.b64 %0, {%1, %2};" : "=l"(r) : "f"(lo), "f"(hi)); return r;
}
__device__ __forceinline__ void unpack2(u64 v, float& lo, float& hi) {
    asm("mov.b64 {%0, %1}, %2;" : "=f"(lo), "=f"(hi) : "l"(v));
}
__device__ __forceinline__ u64 fma2(u64 a, u64 b, u64 c) {
    u64 d; asm("fma.rn.f32x2 %0, %1, %2, %3;" : "=l"(d) : "l"(a), "l"(b), "l"(c)); return d;
}
__device__ __forceinline__ u64 add2(u64 a, u64 b) {
    u64 d; asm("add.rn.f32x2 %0, %1, %2;" : "=l"(d) : "l"(a), "l"(b)); return d;
}

#define BETA2 0x3F6666663F666666ull  // {0.9f, 0.9f}

// packed LIF; per-lane bits identical to: r=(m>1); m=fma(0.9,m,cur)-r; s=(m>1)
__device__ __forceinline__ u64 lif2(u64& m2, u64 cur2) {
    float m0, m1;
    unpack2(m2, m0, m1);
    float r0 = (m0 > 1.0f) ? -1.0f : 0.0f;
    float r1 = (m1 > 1.0f) ? -1.0f : 0.0f;
    m2 = add2(fma2(BETA2, m2, cur2), pack2(r0, r1));
    float n0, n1;
    unpack2(m2, n0, n1);
    return pack2((n0 > 1.0f) ? 1.0f : 0.0f, (n1 > 1.0f) ? 1.0f : 0.0f);
}

__device__ __forceinline__ float lif(float& m, float cur) {
    float r = (m > 1.0f) ? 1.0f : 0.0f;
    m = __fmaf_rn(0.9f, m, cur) - r;
    return (m > 1.0f) ? 1.0f : 0.0f;
}

__global__ __launch_bounds__(THREADS, 1) void snn_kernel(
    const float* __restrict__ x,
    const float* __restrict__ Wsh, const float* __restrict__ bsh,
    const float* __restrict__ Wch, const float* __restrict__ bch,
    const float* __restrict__ Wco, const float* __restrict__ bco,
    const float* __restrict__ Wrh, const float* __restrict__ brh,
    const float* __restrict__ Wro, const float* __restrict__ bro,
    float* __restrict__ out, int B)
{
    __shared__ __align__(16) float swf[SW_FLOATS];
    u64* swu = (u64*)swf;
    const int tid = threadIdx.x;

    for (int i = tid; i < SW_FLOATS; i += THREADS) swf[i] = 0.0f;
    __syncthreads();

    // L1 pairs: swu[U_W1 + i*14 + p] = {Wsh[2p][i], Wsh[2p+1][i]}
    for (int idx = tid; idx < 32 * 14; idx += THREADS) {
        int i = idx / 14, p = idx % 14;
        swf[2 * (U_W1 + idx) + 0] = Wsh[(2 * p) * NIN + i];
        swf[2 * (U_W1 + idx) + 1] = Wsh[(2 * p + 1) * NIN + i];
    }
    for (int p = tid; p < 14; p += THREADS) {
        swf[2 * (U_B1 + p) + 0] = bsh[2 * p];
        swf[2 * (U_B1 + p) + 1] = bsh[2 * p + 1];
    }
    // fused L2+L4 pairs: p 0..3 class hidden, 4..10 reg hidden, 11 pad
    for (int idx = tid; idx < 28 * 11; idx += THREADS) {
        int i = idx / 11, p = idx % 11;
        int u = U_W24 + i * 12 + p;
        if (p < 4) {
            swf[2 * u + 0] = Wch[(2 * p) * 28 + i];
            swf[2 * u + 1] = Wch[(2 * p + 1) * 28 + i];
        } else {
            int q = p - 4;
            swf[2 * u + 0] = Wrh[(2 * q) * 28 + i];
            swf[2 * u + 1] = Wrh[(2 * q + 1) * 28 + i];
        }
    }
    for (int p = tid; p < 11; p += THREADS) {
        if (p < 4) {
            swf[2 * (U_B24 + p) + 0] = bch[2 * p];
            swf[2 * (U_B24 + p) + 1] = bch[2 * p + 1];
        } else {
            int q = p - 4;
            swf[2 * (U_B24 + p) + 0] = brh[2 * q];
            swf[2 * (U_B24 + p) + 1] = brh[2 * q + 1];
        }
    }
    // L3 pairs: [i][p]: p0={Wco0,Wco1}, p1={Wco2,0}
    for (int i = tid; i < 8; i += THREADS) {
        swf[2 * (U_W3 + 2 * i) + 0] = Wco[0 * 8 + i];
        swf[2 * (U_W3 + 2 * i) + 1] = Wco[1 * 8 + i];
        swf[2 * (U_W3 + 2 * i + 1) + 0] = Wco[2 * 8 + i];
    }
    if (tid == 0) {
        swf[2 * U_B3 + 0] = bco[0];
        swf[2 * U_B3 + 1] = bco[1];
        swf[2 * (U_B3 + 1) + 0] = bco[2];
        swf[F_B5] = bro[0];
    }
    for (int i = tid; i < 14; i += THREADS) swf[F_W5 + i] = Wro[i];
    __syncthreads();

    const int pair = blockIdx.x * THREADS + tid;
    if (2 * pair >= B) return;
    const int bA = 2 * pair;

    // membranes: A and B batch, packed per neuron-pair
    u64 mshA[14], mshB[14], mbhA[11], mbhB[11];
    u64 mC0A = 0ull, mC1A = 0ull, mC0B = 0ull, mC1B = 0ull;
    float mroA = 0.0f, mroB = 0.0f;
#pragma unroll
    for (int p = 0; p < 14; p++) { mshA[p] = 0ull; mshB[p] = 0ull; }
#pragma unroll
    for (int p = 0; p < 11; p++) { mbhA[p] = 0ull; mbhB[p] = 0ull; }

    const size_t TB = (size_t)TT * B;
    float* p_mco = out;                 // [T,B,3]
    float* p_sch = out + TB * 3;        // [T,B,8]
    float* p_mro = out + TB * 11;       // [T,B,1]
    float* p_srh = out + TB * 12;       // [T,B,14]
    float* p_ssh = out + TB * 26;       // [T,B,28]

    const size_t xstep = (size_t)B * NIN;

#pragma unroll 1
    for (int t = 0; t < TT; t++) {
        const float* xp = x + (size_t)t * xstep + (size_t)bA * NIN;
        // prefetch next step's two x rows (2 x 128B lines)
        if (t + 1 < TT) {
            asm volatile("prefetch.global.L2 [%0];" :: "l"(xp + xstep));
            asm volatile("prefetch.global.L2 [%0];" :: "l"(xp + xstep + NIN));
        }

        // ---- Layer 1: 14 output-pairs x 2 batches <- 32 inputs ----
        u64 accA[14], accB[14];
#pragma unroll
        for (int p = 0; p < 14; p++) { accA[p] = 0ull; accB[p] = 0ull; }
#pragma unroll
        for (int k = 0; k < 8; k++) {
            float4 a4 = __ldcs((const float4*)xp + k);
            float4 b4 = __ldcs((const float4*)(xp + NIN) + k);
            const float av[4] = {a4.x, a4.y, a4.z, a4.w};
            const float bv[4] = {b4.x, b4.y, b4.z, b4.w};
#pragma unroll
            for (int j = 0; j < 4; j++) {
                u64 dA = pack2(av[j], av[j]);
                u64 dB = pack2(bv[j], bv[j]);
                const u64* w = swu + U_W1 + (4 * k + j) * 14;
#pragma unroll
                for (int pp = 0; pp < 7; pp++) {
                    ulonglong2 wp = *(const ulonglong2*)(w + 2 * pp);
                    accA[2 * pp]     = fma2(dA, wp.x, accA[2 * pp]);
                    accA[2 * pp + 1] = fma2(dA, wp.y, accA[2 * pp + 1]);
                    accB[2 * pp]     = fma2(dB, wp.x, accB[2 * pp]);
                    accB[2 * pp + 1] = fma2(dB, wp.y, accB[2 * pp + 1]);
                }
            }
        }

        // LIF + immediate store + compress spikes to bitmasks
        u32 maskA = 0u, maskB = 0u;
        {
            float* pA = p_ssh + ((size_t)t * B + bA) * 28;  // B row at +28
#pragma unroll
            for (int h = 0; h < 7; h++) {   // 2 pairs per iteration
                u64 s0 = lif2(mshA[2 * h],     add2(accA[2 * h],     swu[U_B1 + 2 * h]));
                u64 s1 = lif2(mshA[2 * h + 1], add2(accA[2 * h + 1], swu[U_B1 + 2 * h + 1]));
                float a, b, c, d;
                unpack2(s0, a, b); unpack2(s1, c, d);
                __stcs((float4*)pA + h, make_float4(a, b, c, d));
                maskA |= (a != 0.0f ? 1u : 0u) << (4 * h);
                maskA |= (b != 0.0f ? 1u : 0u) << (4 * h + 1);
                maskA |= (c != 0.0f ? 1u : 0u) << (4 * h + 2);
                maskA |= (d != 0.0f ? 1u : 0u) << (4 * h + 3);
            }
#pragma unroll
            for (int h = 0; h < 7; h++) {
                u64 s0 = lif2(mshB[2 * h],     add2(accB[2 * h],     swu[U_B1 + 2 * h]));
                u64 s1 = lif2(mshB[2 * h + 1], add2(accB[2 * h + 1], swu[U_B1 + 2 * h + 1]));
                float a, b, c, d;
                unpack2(s0, a, b); unpack2(s1, c, d);
                __stcs((float4*)pA + 7 + h, make_float4(a, b, c, d));
                maskB |= (a != 0.0f ? 1u : 0u) << (4 * h);
                maskB |= (b != 0.0f ? 1u : 0u) << (4 * h + 1);
                maskB |= (c != 0.0f ? 1u : 0u) << (4 * h + 2);
                maskB |= (d != 0.0f ? 1u : 0u) << (4 * h + 3);
            }
        }

        // ---- fused Layers 2+4: 11 output-pairs x 2 batches <- 28 spikes ----
        u64 aA[11], aB[11];
#pragma unroll
        for (int p = 0; p < 11; p++) { aA[p] = 0ull; aB[p] = 0ull; }
#pragma unroll
        for (int i = 0; i < 28; i++) {
            float sA = ((maskA >> i) & 1u) ? 1.0f : 0.0f;
            float sB = ((maskB >> i) & 1u) ? 1.0f : 0.0f;
            u64 dA = pack2(sA, sA);
            u64 dB = pack2(sB, sB);
            const u64* w = swu + U_W24 + i * 12;
#pragma unroll
            for (int pp = 0; pp < 5; pp++) {
                ulonglong2 wp = *(const ulonglong2*)(w + 2 * pp);
                aA[2 * pp]     = fma2(dA, wp.x, aA[2 * pp]);
                aA[2 * pp + 1] = fma2(dA, wp.y, aA[2 * pp + 1]);
                aB[2 * pp]     = fma2(dB, wp.x, aB[2 * pp]);
                aB[2 * pp + 1] = fma2(dB, wp.y, aB[2 * pp + 1]);
            }
            ulonglong2 wl = *(const ulonglong2*)(w + 10);  // row10 + zero pad
            aA[10] = fma2(dA, wl.x, aA[10]);
            aB[10] = fma2(dB, wl.x, aB[10]);
        }
        u64 spcA[4], spcB[4], sprA[7], sprB[7];
#pragma unroll
        for (int p = 0; p < 4; p++) {
            spcA[p] = lif2(mbhA[p], add2(aA[p], swu[U_B24 + p]));
            spcB[p] = lif2(mbhB[p], add2(aB[p], swu[U_B24 + p]));
        }
#pragma unroll
        for (int p = 0; p < 7; p++) {
            sprA[p] = lif2(mbhA[4 + p], add2(aA[4 + p], swu[U_B24 + 4 + p]));
            sprB[p] = lif2(mbhB[4 + p], add2(aB[4 + p], swu[U_B24 + 4 + p]));
        }

        // store spk_ch: 16 floats (A 8, B 8)
        {
            float* p = p_sch + ((size_t)t * B + bA) * 8;
            float a, b, c, d;
            unpack2(spcA[0], a, b); unpack2(spcA[1], c, d);
            __stcs((float4*)p, make_float4(a, b, c, d));
            unpack2(spcA[2], a, b); unpack2(spcA[3], c, d);
            __stcs((float4*)p + 1, make_float4(a, b, c, d));
            unpack2(spcB[0], a, b); unpack2(spcB[1], c, d);
            __stcs((float4*)p + 2, make_float4(a, b, c, d));
            unpack2(spcB[2], a, b); unpack2(spcB[3], c, d);
            __stcs((float4*)p + 3, make_float4(a, b, c, d));
        }
        // store spk_rh: 28 floats (A 14, B 14) as 7 float4
        {
            float v[28];
#pragma unroll
            for (int p = 0; p < 7; p++) {
                unpack2(sprA[p], v[2 * p], v[2 * p + 1]);
                unpack2(sprB[p], v[14 + 2 * p], v[14 + 2 * p + 1]);
            }
            float* p = p_srh + ((size_t)t * B + bA) * 14;
#pragma unroll
            for (int h = 0; h < 7; h++)
                __stcs((float4*)p + h,
                       make_float4(v[4 * h], v[4 * h + 1], v[4 * h + 2], v[4 * h + 3]));
        }

        // ---- Layer 3: class out, 2 output-pairs (o0,o1),(o2,pad) ----
        {
            float cA[8], cB[8];
            unpack2(spcA[0], cA[0], cA[1]); unpack2(spcA[1], cA[2], cA[3]);
            unpack2(spcA[2], cA[4], cA[5]); unpack2(spcA[3], cA[6], cA[7]);
            unpack2(spcB[0], cB[0], cB[1]); unpack2(spcB[1], cB[2], cB[3]);
            unpack2(spcB[2], cB[4], cB[5]); unpack2(spcB[3], cB[6], cB[7]);
            u64 c0A = 0ull, c1A = 0ull, c0B = 0ull, c1B = 0ull;
#pragma unroll
            for (int i = 0; i < 8; i++) {
                ulonglong2 wp = *(const ulonglong2*)(swu + U_W3 + 2 * i);
                u64 dA = pack2(cA[i], cA[i]);
                u64 dB = pack2(cB[i], cB[i]);
                c0A = fma2(dA, wp.x, c0A); c1A = fma2(dA, wp.y, c1A);
                c0B = fma2(dB, wp.x, c0B); c1B = fma2(dB, wp.y, c1B);
            }
            (void)lif2(mC0A, add2(c0A, swu[U_B3]));
            (void)lif2(mC1A, add2(c1A, swu[U_B3 + 1]));
            (void)lif2(mC0B, add2(c0B, swu[U_B3]));
            (void)lif2(mC1B, add2(c1B, swu[U_B3 + 1]));
            float a0, a1, a2, pd, b0, b1, b2;
            unpack2(mC0A, a0, a1); unpack2(mC1A, a2, pd);
            unpack2(mC0B, b0, b1); unpack2(mC1B, b2, pd);
            float* p = p_mco + ((size_t)t * B + bA) * 3;
            __stcs((float2*)p,     make_float2(a0, a1));
            __stcs((float2*)p + 1, make_float2(a2, b0));
            __stcs((float2*)p + 2, make_float2(b1, b2));
        }

        // ---- Layer 5: reg out (scalar), both batches share weight regs ----
        {
            float rA[14], rB[14];
#pragma unroll
            for (int p = 0; p < 7; p++) {
                unpack2(sprA[p], rA[2 * p], rA[2 * p + 1]);
                unpack2(sprB[p], rB[2 * p], rB[2 * p + 1]);
            }
            float4 w0 = *(const float4*)(swf + F_W5);
            float4 w1 = *(const float4*)(swf + F_W5 + 4);
            float4 w2 = *(const float4*)(swf + F_W5 + 8);
            float2 w3 = *(const float2*)(swf + F_W5 + 12);
            const float wv[14] = {w0.x, w0.y, w0.z, w0.w, w1.x, w1.y, w1.z, w1.w,
                                  w2.x, w2.y, w2.z, w2.w, w3.x, w3.y};
            float a = 0.0f, b = 0.0f;
#pragma unroll
            for (int i = 0; i < 14; i++) {
                a = __fmaf_rn(rA[i], wv[i], a);
                b = __fmaf_rn(rB[i], wv[i], b);
            }
            (void)lif(mroA, a + swf[F_B5]);
            (void)lif(mroB, b + swf[F_B5]);
            __stcs((float2*)(p_mro + (size_t)t * B + bA), make_float2(mroA, mroB));
        }
    }
}

extern "C" void kernel_launch(void* const* d_in, const int* in_sizes, int n_in,
                              void* d_out, int out_size) {
    const float* x   = (const float*)d_in[0];
    const float* Wsh = (const float*)d_in[1];
    const float* bsh = (const float*)d_in[2];
    const float* Wch = (const float*)d_in[3];
    const float* bch = (const float*)d_in[4];
    const float* Wco = (const float*)d_in[5];
    const float* bco = (const float*)d_in[6];
    const float* Wrh = (const float*)d_in[7];
    const float* brh = (const float*)d_in[8];
    const float* Wro = (const float*)d_in[9];
    const float* bro = (const float*)d_in[10];

    const int B = in_sizes[0] / (TT * NIN);
    const int pairs = B / 2;
    const int blocks = (pairs + THREADS - 1) / THREADS;

    snn_kernel<<<blocks, THREADS>>>(x, Wsh, bsh, Wch, bch, Wco, bco,
                                    Wrh, brh, Wro, bro, (float*)d_out, B);
}

// round 9
// speedup vs baseline: 1.3884x; 1.3884x over previous
#include <cuda_runtime.h>

// ---------------------------------------------------------------------------
// MultitaskSNN round 9: round-8 design with store-alignment fix.
// Each thread: 2 batch elements x half the neurons. Thread pair (even h=0,
// odd h=1) covers one batch pair: h0 owns shared-hidden neurons 0..13 +
// class branch, h1 owns 14..27 + regression branch, padded to identical
// instruction streams. Weight pairs {w[o],w[o+1]} loaded once per thread
// serve BOTH batches. Spikes cross the thread pair via one SHFL.BFLY mask.
// Fix vs round 8: spk_rh B-row base is only 8B-aligned -> float2 stores.
// Per-neuron arithmetic (ascending-i chain, bias after sum,
// fma(0.9,m,cur)-reset) is unchanged -> bit-exact vs reference.
// ---------------------------------------------------------------------------

typedef unsigned long long u64;
typedef unsigned int u32;

#define TT 50
#define NIN 32
#define THREADS 224

// u64-unit smem offsets
#define UW1  0      // [i=32][slot=16]: slots 0-6 h0 pairs, 8-14 h1 pairs
#define UB1  512    // [slot=16]
#define UW24 528    // [i=28][slot=16]: 0-6 h0 (class 4 + 3 pad), 8-14 h1 (reg 7)
#define UB24 976    // [slot=16]
#define UW5  992    // [i=14][slot=4]: 0={co0,co1} 1={co2,0} 2={ro,0} 3={0,0}
#define UB5  1048   // [slot=4]
#define SW_U64 1052

__device__ __forceinline__ u64 pack2(float lo, float hi) {
    u64 r; asm("mov.b64 %0, {%1, %2};" : "=l"(r) : "f"(lo), "f"(hi)); return r;
}
__device__ __forceinline__ void unpack2(u64 v, float& lo, float& hi) {
    asm("mov.b64 {%0, %1}, %2;" : "=f"(lo), "=f"(hi) : "l"(v));
}
__device__ __forceinline__ u64 fma2(u64 a, u64 b, u64 c) {
    u64 d; asm("fma.rn.f32x2 %0, %1, %2, %3;" : "=l"(d) : "l"(a), "l"(b), "l"(c)); return d;
}
__device__ __forceinline__ u64 add2(u64 a, u64 b) {
    u64 d; asm("add.rn.f32x2 %0, %1, %2;" : "=l"(d) : "l"(a), "l"(b)); return d;
}

#define BETA2 0x3F6666663F666666ull  // {0.9f, 0.9f}

// packed LIF; per-lane bits identical to: r=(m>1); m=fma(0.9,m,cur)-r; s=(m>1)
__device__ __forceinline__ u64 lif2(u64& m2, u64 cur2) {
    float m0, m1;
    unpack2(m2, m0, m1);
    float r0 = (m0 > 1.0f) ? -1.0f : 0.0f;
    float r1 = (m1 > 1.0f) ? -1.0f : 0.0f;
    m2 = add2(fma2(BETA2, m2, cur2), pack2(r0, r1));
    float n0, n1;
    unpack2(m2, n0, n1);
    return pack2((n0 > 1.0f) ? 1.0f : 0.0f, (n1 > 1.0f) ? 1.0f : 0.0f);
}

__global__ __launch_bounds__(THREADS, 1) void snn_kernel(
    const float* __restrict__ x,
    const float* __restrict__ Wsh, const float* __restrict__ bsh,
    const float* __restrict__ Wch, const float* __restrict__ bch,
    const float* __restrict__ Wco, const float* __restrict__ bco,
    const float* __restrict__ Wrh, const float* __restrict__ brh,
    const float* __restrict__ Wro, const float* __restrict__ bro,
    float* __restrict__ out, int B)
{
    __shared__ __align__(16) u64 swu[SW_U64];
    float* swf = (float*)swu;
    const int tid = threadIdx.x;

    for (int i = tid; i < SW_U64; i += THREADS) swu[i] = 0ull;
    __syncthreads();

    // L1 pairs: slot = 8h + pp holds {Wsh[14h+2pp][i], Wsh[14h+2pp+1][i]}
    for (int idx = tid; idx < 32 * 14; idx += THREADS) {
        int i = idx / 14, p = idx % 14, hh = p / 7, pp = p % 7;
        int o = 14 * hh + 2 * pp;
        int u = UW1 + i * 16 + 8 * hh + pp;
        swf[2 * u + 0] = Wsh[o * NIN + i];
        swf[2 * u + 1] = Wsh[(o + 1) * NIN + i];
    }
    for (int p = tid; p < 14; p += THREADS) {
        int hh = p / 7, pp = p % 7, o = 14 * hh + 2 * pp;
        swf[2 * (UB1 + 8 * hh + pp) + 0] = bsh[o];
        swf[2 * (UB1 + 8 * hh + pp) + 1] = bsh[o + 1];
    }
    // branch weights: class (h0, slots 0-3), reg (h1, slots 8-14)
    for (int idx = tid; idx < 8 * 28; idx += THREADS) {
        int o = idx / 28, i = idx % 28;
        swf[2 * (UW24 + i * 16 + (o >> 1)) + (o & 1)] = Wch[idx];
    }
    for (int idx = tid; idx < 14 * 28; idx += THREADS) {
        int o = idx / 28, i = idx % 28;
        swf[2 * (UW24 + i * 16 + 8 + (o >> 1)) + (o & 1)] = Wrh[idx];
    }
    for (int o = tid; o < 8; o += THREADS)
        swf[2 * (UB24 + (o >> 1)) + (o & 1)] = bch[o];
    for (int o = tid; o < 14; o += THREADS)
        swf[2 * (UB24 + 8 + (o >> 1)) + (o & 1)] = brh[o];
    // out layer
    for (int i = tid; i < 8; i += THREADS) {
        swf[2 * (UW5 + i * 4 + 0) + 0] = Wco[0 * 8 + i];
        swf[2 * (UW5 + i * 4 + 0) + 1] = Wco[1 * 8 + i];
        swf[2 * (UW5 + i * 4 + 1) + 0] = Wco[2 * 8 + i];
    }
    for (int i = tid; i < 14; i += THREADS)
        swf[2 * (UW5 + i * 4 + 2) + 0] = Wro[i];
    if (tid == 0) {
        swf[2 * (UB5 + 0) + 0] = bco[0];
        swf[2 * (UB5 + 0) + 1] = bco[1];
        swf[2 * (UB5 + 1) + 0] = bco[2];
        swf[2 * (UB5 + 2) + 0] = bro[0];
    }
    __syncthreads();

    const int gid = blockIdx.x * THREADS + tid;
    if (gid >= B) return;              // whole warps exit together
    const int h  = gid & 1;
    const int bA = gid & ~1;           // batch pair base (even)

    const u64* w1  = swu + UW1  + 8 * h;
    const u64* b1  = swu + UB1  + 8 * h;
    const u64* w24 = swu + UW24 + 8 * h;
    const u64* b24 = swu + UB24 + 8 * h;
    const u64* w5  = swu + UW5  + 2 * h;
    const u64* b5  = swu + UB5  + 2 * h;

    u64 msA[7], msB[7], mbA[7], mbB[7];
    u64 moA0 = 0ull, moA1 = 0ull, moB0 = 0ull, moB1 = 0ull;
#pragma unroll
    for (int p = 0; p < 7; p++) { msA[p] = 0ull; msB[p] = 0ull; mbA[p] = 0ull; mbB[p] = 0ull; }

    const size_t TB = (size_t)TT * B;
    float* p_mco = out;                 // [T,B,3]
    float* p_sch = out + TB * 3;        // [T,B,8]
    float* p_mro = out + TB * 11;       // [T,B,1]
    float* p_srh = out + TB * 12;       // [T,B,14]
    float* p_ssh = out + TB * 26;       // [T,B,28]

    const size_t xstep = (size_t)B * NIN;
    const float* xbase = x + (size_t)bA * NIN;

#pragma unroll 1
    for (int t = 0; t < TT; t++) {
        const float* xp = xbase + (size_t)t * xstep;
        if (t + 1 < TT) {
            asm volatile("prefetch.global.L2 [%0];" :: "l"(xp + xstep));
            asm volatile("prefetch.global.L2 [%0];" :: "l"(xp + xstep + NIN));
        }

        // ---- Layer 1: 7 neuron-pairs x 2 batches <- 32 inputs ----
        u64 aA[7], aB[7];
#pragma unroll
        for (int p = 0; p < 7; p++) { aA[p] = 0ull; aB[p] = 0ull; }
#pragma unroll
        for (int k = 0; k < 8; k++) {
            float4 a4 = __ldcs((const float4*)xp + k);
            float4 b4 = __ldcs((const float4*)(xp + NIN) + k);
            const float av[4] = {a4.x, a4.y, a4.z, a4.w};
            const float bv[4] = {b4.x, b4.y, b4.z, b4.w};
#pragma unroll
            for (int j = 0; j < 4; j++) {
                u64 dA = pack2(av[j], av[j]);
                u64 dB = pack2(bv[j], bv[j]);
                const u64* w = w1 + (4 * k + j) * 16;
                ulonglong2 w01 = *(const ulonglong2*)(w);
                ulonglong2 w23 = *(const ulonglong2*)(w + 2);
                ulonglong2 w45 = *(const ulonglong2*)(w + 4);
                u64 w6 = w[6];
                aA[0] = fma2(dA, w01.x, aA[0]); aB[0] = fma2(dB, w01.x, aB[0]);
                aA[1] = fma2(dA, w01.y, aA[1]); aB[1] = fma2(dB, w01.y, aB[1]);
                aA[2] = fma2(dA, w23.x, aA[2]); aB[2] = fma2(dB, w23.x, aB[2]);
                aA[3] = fma2(dA, w23.y, aA[3]); aB[3] = fma2(dB, w23.y, aB[3]);
                aA[4] = fma2(dA, w45.x, aA[4]); aB[4] = fma2(dB, w45.x, aB[4]);
                aA[5] = fma2(dA, w45.y, aA[5]); aB[5] = fma2(dB, w45.y, aB[5]);
                aA[6] = fma2(dA, w6,    aA[6]); aB[6] = fma2(dB, w6,    aB[6]);
            }
        }

        // LIF + store spk_sh (own 14 columns per batch) + build masks
        u32 mA = 0u, mB = 0u;
        {
            float* pA = p_ssh + ((size_t)t * B + bA) * 28 + 14 * h;  // 8B aligned
            float* pB = pA + 28;
#pragma unroll
            for (int p = 0; p < 7; p++) {
                u64 sA = lif2(msA[p], add2(aA[p], b1[p]));
                u64 sB = lif2(msB[p], add2(aB[p], b1[p]));
                float a0, a1, b0, b1f;
                unpack2(sA, a0, a1);
                unpack2(sB, b0, b1f);
                __stcs((float2*)pA + p, make_float2(a0, a1));
                __stcs((float2*)pB + p, make_float2(b0, b1f));
                mA |= (a0 != 0.0f ? 1u : 0u) << (2 * p);
                mA |= (a1 != 0.0f ? 1u : 0u) << (2 * p + 1);
                mB |= (b0 != 0.0f ? 1u : 0u) << (2 * p);
                mB |= (b1f != 0.0f ? 1u : 0u) << (2 * p + 1);
            }
        }

        // ---- exchange spike masks with partner thread ----
        u32 ex = mA | (mB << 16);
        u32 pt = __shfl_xor_sync(0xffffffffu, ex, 1);
        u32 fullA = (mA << (14 * h)) | ((pt & 0x3FFFu) << (14 * (1 - h)));
        u32 fullB = (mB << (14 * h)) | (((pt >> 16) & 0x3FFFu) << (14 * (1 - h)));

        // ---- branch layer: 7 neuron-pairs x 2 batches <- 28 spikes ----
        u64 cA[7], cB[7];
#pragma unroll
        for (int p = 0; p < 7; p++) { cA[p] = 0ull; cB[p] = 0ull; }
#pragma unroll
        for (int i = 0; i < 28; i++) {
            float sA = ((fullA >> i) & 1u) ? 1.0f : 0.0f;
            float sB = ((fullB >> i) & 1u) ? 1.0f : 0.0f;
            u64 dA = pack2(sA, sA);
            u64 dB = pack2(sB, sB);
            const u64* w = w24 + i * 16;
            ulonglong2 w01 = *(const ulonglong2*)(w);
            ulonglong2 w23 = *(const ulonglong2*)(w + 2);
            ulonglong2 w45 = *(const ulonglong2*)(w + 4);
            u64 w6 = w[6];
            cA[0] = fma2(dA, w01.x, cA[0]); cB[0] = fma2(dB, w01.x, cB[0]);
            cA[1] = fma2(dA, w01.y, cA[1]); cB[1] = fma2(dB, w01.y, cB[1]);
            cA[2] = fma2(dA, w23.x, cA[2]); cB[2] = fma2(dB, w23.x, cB[2]);
            cA[3] = fma2(dA, w23.y, cA[3]); cB[3] = fma2(dB, w23.y, cB[3]);
            cA[4] = fma2(dA, w45.x, cA[4]); cB[4] = fma2(dB, w45.x, cB[4]);
            cA[5] = fma2(dA, w45.y, cA[5]); cB[5] = fma2(dB, w45.y, cB[5]);
            cA[6] = fma2(dA, w6,    cA[6]); cB[6] = fma2(dB, w6,    cB[6]);
        }
        float fA[14], fB[14];
#pragma unroll
        for (int p = 0; p < 7; p++) {
            u64 sA = lif2(mbA[p], add2(cA[p], b24[p]));
            u64 sB = lif2(mbB[p], add2(cB[p], b24[p]));
            unpack2(sA, fA[2 * p], fA[2 * p + 1]);
            unpack2(sB, fB[2 * p], fB[2 * p + 1]);
        }

        // branch spike stores (divergent, small)
        if (h == 0) {
            // base (t*B+bA)*8 floats -> 32B aligned: float4 OK
            float* p = p_sch + ((size_t)t * B + bA) * 8;
            __stcs((float4*)p,     make_float4(fA[0], fA[1], fA[2], fA[3]));
            __stcs((float4*)p + 1, make_float4(fA[4], fA[5], fA[6], fA[7]));
            __stcs((float4*)p + 2, make_float4(fB[0], fB[1], fB[2], fB[3]));
            __stcs((float4*)p + 3, make_float4(fB[4], fB[5], fB[6], fB[7]));
        } else {
            // base (t*B+bA)*14 floats: even*14 -> 8B aligned only: float2 stores
            float* p = p_srh + ((size_t)t * B + bA) * 14;
#pragma unroll
            for (int k = 0; k < 7; k++)
                __stcs((float2*)p + k, make_float2(fA[2 * k], fA[2 * k + 1]));
            float* q = p + 14;
#pragma unroll
            for (int k = 0; k < 7; k++)
                __stcs((float2*)q + k, make_float2(fB[2 * k], fB[2 * k + 1]));
        }

        // ---- out layer: 2 output-pairs x 2 batches <- 14 own spikes ----
        u64 oA0 = 0ull, oA1 = 0ull, oB0 = 0ull, oB1 = 0ull;
#pragma unroll
        for (int i = 0; i < 14; i++) {
            u64 dA = pack2(fA[i], fA[i]);
            u64 dB = pack2(fB[i], fB[i]);
            ulonglong2 wp = *(const ulonglong2*)(w5 + i * 4);
            oA0 = fma2(dA, wp.x, oA0); oA1 = fma2(dA, wp.y, oA1);
            oB0 = fma2(dB, wp.x, oB0); oB1 = fma2(dB, wp.y, oB1);
        }
        (void)lif2(moA0, add2(oA0, b5[0]));
        (void)lif2(moA1, add2(oA1, b5[1]));
        (void)lif2(moB0, add2(oB0, b5[0]));
        (void)lif2(moB1, add2(oB1, b5[1]));

        if (h == 0) {
            // base (t*B+bA)*3 floats: even*3 -> 8B aligned: float2 stores
            float a0, a1, a2, pd, b0, b1f, b2;
            unpack2(moA0, a0, a1); unpack2(moA1, a2, pd);
            unpack2(moB0, b0, b1f); unpack2(moB1, b2, pd);
            float* p = p_mco + ((size_t)t * B + bA) * 3;
            __stcs((float2*)p,     make_float2(a0, a1));
            __stcs((float2*)p + 1, make_float2(a2, b0));
            __stcs((float2*)p + 2, make_float2(b1f, b2));
        } else {
            float rA, rB, pd;
            unpack2(moA0, rA, pd);
            unpack2(moB0, rB, pd);
            // base (t*B+bA) even -> 8B aligned: float2 OK
            __stcs((float2*)(p_mro + (size_t)t * B + bA), make_float2(rA, rB));
        }
    }
}

extern "C" void kernel_launch(void* const* d_in, const int* in_sizes, int n_in,
                              void* d_out, int out_size) {
    const float* x   = (const float*)d_in[0];
    const float* Wsh = (const float*)d_in[1];
    const float* bsh = (const float*)d_in[2];
    const float* Wch = (const float*)d_in[3];
    const float* bch = (const float*)d_in[4];
    const float* Wco = (const float*)d_in[5];
    const float* bco = (const float*)d_in[6];
    const float* Wrh = (const float*)d_in[7];
    const float* brh = (const float*)d_in[8];
    const float* Wro = (const float*)d_in[9];
    const float* bro = (const float*)d_in[10];

    const int B = in_sizes[0] / (TT * NIN);
    const int blocks = (B + THREADS - 1) / THREADS;   // threads == B

    snn_kernel<<<blocks, THREADS>>>(x, Wsh, bsh, Wch, bch, Wco, bco,
                                    Wrh, brh, Wro, bro, (float*)d_out, B);
}

// round 10
// speedup vs baseline: 1.4418x; 1.0384x over previous
#include <cuda_runtime.h>

// ---------------------------------------------------------------------------
// MultitaskSNN round 10: R9 frame (2 batches x half-neurons per thread,
// 224 thr x 147 blocks, halved SMEM weight traffic) with latency surgery:
//  1. spike-carry LIF: reset_t == spk_{t-1}, so carry s and compute
//     m = fma2(s, {-1,-1}, fma2(beta, m, cur))  (bit-exact).
//  2. direct SHFL exchange of spike u64 pairs (masks + bit-extract deleted).
//  3. branch/out layers use dup-pack FFMA2 on spike scalars (R4/R6 pattern).
// Per-neuron arithmetic order unchanged -> bit-exact vs reference.
// ---------------------------------------------------------------------------

typedef unsigned long long u64;
typedef unsigned int u32;

#define TT 50
#define NIN 32
#define THREADS 224

// u64-unit smem offsets
#define UW1  0      // [i=32][slot=16]: slots 0-6 h0 pairs, 8-14 h1 pairs
#define UB1  512    // [slot=16]
#define UW24 528    // [i=28][slot=16]: 0-6 h0 (class 4 + 3 pad), 8-14 h1 (reg 7)
#define UB24 976    // [slot=16]
#define UW5  992    // [i=14][slot=4]: 0={co0,co1} 1={co2,0} 2={ro,0} 3={0,0}
#define UB5  1048   // [slot=4]
#define SW_U64 1052

__device__ __forceinline__ u64 pack2(float lo, float hi) {
    u64 r; asm("mov.b64 %0, {%1, %2};" : "=l"(r) : "f"(lo), "f"(hi)); return r;
}
__device__ __forceinline__ void unpack2(u64 v, float& lo, float& hi) {
    asm("mov.b64 {%0, %1}, %2;" : "=f"(lo), "=f"(hi) : "l"(v));
}
__device__ __forceinline__ u64 fma2(u64 a, u64 b, u64 c) {
    u64 d; asm("fma.rn.f32x2 %0, %1, %2, %3;" : "=l"(d) : "l"(a), "l"(b), "l"(c)); return d;
}
__device__ __forceinline__ u64 add2(u64 a, u64 b) {
    u64 d; asm("add.rn.f32x2 %0, %1, %2;" : "=l"(d) : "l"(a), "l"(b)); return d;
}

#define BETA2  0x3F6666663F666666ull  // {0.9f, 0.9f}
#define NEG1X2 0xBF800000BF800000ull  // {-1.f, -1.f}

// spike-carry LIF: m = fma(s_prev, -1, fma(beta, m, cur)); s = (m > 1)
// Bit-exact vs reference: reset_t = spike(mem_{t-1}-1) == spk_{t-1} = s_prev;
// fma(1,-1,z) = rn(z-1) (exact sub), fma(0,-1,z) = z.
__device__ __forceinline__ u64 lif2(u64& m2, u64 s2, u64 cur2) {
    m2 = fma2(s2, NEG1X2, fma2(BETA2, m2, cur2));
    float n0, n1;
    unpack2(m2, n0, n1);
    return pack2((n0 > 1.0f) ? 1.0f : 0.0f, (n1 > 1.0f) ? 1.0f : 0.0f);
}

__global__ __launch_bounds__(THREADS, 1) void snn_kernel(
    const float* __restrict__ x,
    const float* __restrict__ Wsh, const float* __restrict__ bsh,
    const float* __restrict__ Wch, const float* __restrict__ bch,
    const float* __restrict__ Wco, const float* __restrict__ bco,
    const float* __restrict__ Wrh, const float* __restrict__ brh,
    const float* __restrict__ Wro, const float* __restrict__ bro,
    float* __restrict__ out, int B)
{
    __shared__ __align__(16) u64 swu[SW_U64];
    float* swf = (float*)swu;
    const int tid = threadIdx.x;

    for (int i = tid; i < SW_U64; i += THREADS) swu[i] = 0ull;
    __syncthreads();

    // L1 pairs: slot = 8h + pp holds {Wsh[14h+2pp][i], Wsh[14h+2pp+1][i]}
    for (int idx = tid; idx < 32 * 14; idx += THREADS) {
        int i = idx / 14, p = idx % 14, hh = p / 7, pp = p % 7;
        int o = 14 * hh + 2 * pp;
        int u = UW1 + i * 16 + 8 * hh + pp;
        swf[2 * u + 0] = Wsh[o * NIN + i];
        swf[2 * u + 1] = Wsh[(o + 1) * NIN + i];
    }
    for (int p = tid; p < 14; p += THREADS) {
        int hh = p / 7, pp = p % 7, o = 14 * hh + 2 * pp;
        swf[2 * (UB1 + 8 * hh + pp) + 0] = bsh[o];
        swf[2 * (UB1 + 8 * hh + pp) + 1] = bsh[o + 1];
    }
    // branch weights: class (h0, slots 0-3), reg (h1, slots 8-14)
    for (int idx = tid; idx < 8 * 28; idx += THREADS) {
        int o = idx / 28, i = idx % 28;
        swf[2 * (UW24 + i * 16 + (o >> 1)) + (o & 1)] = Wch[idx];
    }
    for (int idx = tid; idx < 14 * 28; idx += THREADS) {
        int o = idx / 28, i = idx % 28;
        swf[2 * (UW24 + i * 16 + 8 + (o >> 1)) + (o & 1)] = Wrh[idx];
    }
    for (int o = tid; o < 8; o += THREADS)
        swf[2 * (UB24 + (o >> 1)) + (o & 1)] = bch[o];
    for (int o = tid; o < 14; o += THREADS)
        swf[2 * (UB24 + 8 + (o >> 1)) + (o & 1)] = brh[o];
    // out layer
    for (int i = tid; i < 8; i += THREADS) {
        swf[2 * (UW5 + i * 4 + 0) + 0] = Wco[0 * 8 + i];
        swf[2 * (UW5 + i * 4 + 0) + 1] = Wco[1 * 8 + i];
        swf[2 * (UW5 + i * 4 + 1) + 0] = Wco[2 * 8 + i];
    }
    for (int i = tid; i < 14; i += THREADS)
        swf[2 * (UW5 + i * 4 + 2) + 0] = Wro[i];
    if (tid == 0) {
        swf[2 * (UB5 + 0) + 0] = bco[0];
        swf[2 * (UB5 + 0) + 1] = bco[1];
        swf[2 * (UB5 + 1) + 0] = bco[2];
        swf[2 * (UB5 + 2) + 0] = bro[0];
    }
    __syncthreads();

    const int gid = blockIdx.x * THREADS + tid;
    if (gid >= B) return;              // whole warps exit together
    const int h  = gid & 1;
    const int bA = gid & ~1;           // batch pair base (even)

    const u64* w1  = swu + UW1  + 8 * h;
    const u64* b1  = swu + UB1  + 8 * h;
    const u64* w24 = swu + UW24 + 8 * h;
    const u64* b24 = swu + UB24 + 8 * h;
    const u64* w5  = swu + UW5  + 2 * h;
    const u64* b5  = swu + UB5  + 2 * h;

    // membrane + carried-spike state
    u64 msA[7], msB[7], ssA[7], ssB[7];
    u64 mbA[7], mbB[7], sbA[7], sbB[7];
    u64 moA0 = 0ull, moA1 = 0ull, moB0 = 0ull, moB1 = 0ull;
    u64 soA0 = 0ull, soA1 = 0ull, soB0 = 0ull, soB1 = 0ull;
#pragma unroll
    for (int p = 0; p < 7; p++) {
        msA[p] = 0ull; msB[p] = 0ull; ssA[p] = 0ull; ssB[p] = 0ull;
        mbA[p] = 0ull; mbB[p] = 0ull; sbA[p] = 0ull; sbB[p] = 0ull;
    }

    const size_t TB = (size_t)TT * B;
    float* p_mco = out;                 // [T,B,3]
    float* p_sch = out + TB * 3;        // [T,B,8]
    float* p_mro = out + TB * 11;       // [T,B,1]
    float* p_srh = out + TB * 12;       // [T,B,14]
    float* p_ssh = out + TB * 26;       // [T,B,28]

    const size_t xstep = (size_t)B * NIN;
    const float* xbase = x + (size_t)bA * NIN;

#pragma unroll 1
    for (int t = 0; t < TT; t++) {
        const float* xp = xbase + (size_t)t * xstep;
        if (t + 1 < TT) {
            asm volatile("prefetch.global.L2 [%0];" :: "l"(xp + xstep));
            asm volatile("prefetch.global.L2 [%0];" :: "l"(xp + xstep + NIN));
        }

        // ---- Layer 1: 7 neuron-pairs x 2 batches <- 32 inputs ----
        u64 aA[7], aB[7];
#pragma unroll
        for (int p = 0; p < 7; p++) { aA[p] = 0ull; aB[p] = 0ull; }
#pragma unroll
        for (int k = 0; k < 8; k++) {
            float4 a4 = __ldcs((const float4*)xp + k);
            float4 b4 = __ldcs((const float4*)(xp + NIN) + k);
            const float av[4] = {a4.x, a4.y, a4.z, a4.w};
            const float bv[4] = {b4.x, b4.y, b4.z, b4.w};
#pragma unroll
            for (int j = 0; j < 4; j++) {
                u64 dA = pack2(av[j], av[j]);
                u64 dB = pack2(bv[j], bv[j]);
                const u64* w = w1 + (4 * k + j) * 16;
                ulonglong2 w01 = *(const ulonglong2*)(w);
                ulonglong2 w23 = *(const ulonglong2*)(w + 2);
                ulonglong2 w45 = *(const ulonglong2*)(w + 4);
                u64 w6 = w[6];
                aA[0] = fma2(dA, w01.x, aA[0]); aB[0] = fma2(dB, w01.x, aB[0]);
                aA[1] = fma2(dA, w01.y, aA[1]); aB[1] = fma2(dB, w01.y, aB[1]);
                aA[2] = fma2(dA, w23.x, aA[2]); aB[2] = fma2(dB, w23.x, aB[2]);
                aA[3] = fma2(dA, w23.y, aA[3]); aB[3] = fma2(dB, w23.y, aB[3]);
                aA[4] = fma2(dA, w45.x, aA[4]); aB[4] = fma2(dB, w45.x, aB[4]);
                aA[5] = fma2(dA, w45.y, aA[5]); aB[5] = fma2(dB, w45.y, aB[5]);
                aA[6] = fma2(dA, w6,    aA[6]); aB[6] = fma2(dB, w6,    aB[6]);
            }
        }

        // LIF (spike-carry) + store spk_sh
#pragma unroll
        for (int p = 0; p < 7; p++) {
            ssA[p] = lif2(msA[p], ssA[p], add2(aA[p], b1[p]));
            ssB[p] = lif2(msB[p], ssB[p], add2(aB[p], b1[p]));
        }
        {
            float* pA = p_ssh + ((size_t)t * B + bA) * 28 + 14 * h;  // 8B aligned
            float* pB = pA + 28;
#pragma unroll
            for (int p = 0; p < 7; p++) {
                float a0, a1, b0, b1f;
                unpack2(ssA[p], a0, a1);
                unpack2(ssB[p], b0, b1f);
                __stcs((float2*)pA + p, make_float2(a0, a1));
                __stcs((float2*)pB + p, make_float2(b0, b1f));
            }
        }

        // ---- exchange spike pairs with partner thread (direct SHFL) ----
        u64 sAf[14], sBf[14];
#pragma unroll
        for (int p = 0; p < 7; p++) {
            u64 qA = __shfl_xor_sync(0xffffffffu, ssA[p], 1);
            u64 qB = __shfl_xor_sync(0xffffffffu, ssB[p], 1);
            sAf[p]     = h ? qA     : ssA[p];
            sAf[7 + p] = h ? ssA[p] : qA;
            sBf[p]     = h ? qB     : ssB[p];
            sBf[7 + p] = h ? ssB[p] : qB;
        }

        // ---- branch layer: 7 neuron-pairs x 2 batches <- 28 spikes ----
        u64 cA[7], cB[7];
#pragma unroll
        for (int p = 0; p < 7; p++) { cA[p] = 0ull; cB[p] = 0ull; }
#pragma unroll
        for (int pp = 0; pp < 14; pp++) {
            float sa0, sa1, sb0, sb1;
            unpack2(sAf[pp], sa0, sa1);
            unpack2(sBf[pp], sb0, sb1);
#pragma unroll
            for (int half = 0; half < 2; half++) {
                const float sa = half ? sa1 : sa0;
                const float sb = half ? sb1 : sb0;
                const int i = 2 * pp + half;
                u64 dA = pack2(sa, sa);
                u64 dB = pack2(sb, sb);
                const u64* w = w24 + i * 16;
                ulonglong2 w01 = *(const ulonglong2*)(w);
                ulonglong2 w23 = *(const ulonglong2*)(w + 2);
                ulonglong2 w45 = *(const ulonglong2*)(w + 4);
                u64 w6 = w[6];
                cA[0] = fma2(dA, w01.x, cA[0]); cB[0] = fma2(dB, w01.x, cB[0]);
                cA[1] = fma2(dA, w01.y, cA[1]); cB[1] = fma2(dB, w01.y, cB[1]);
                cA[2] = fma2(dA, w23.x, cA[2]); cB[2] = fma2(dB, w23.x, cB[2]);
                cA[3] = fma2(dA, w23.y, cA[3]); cB[3] = fma2(dB, w23.y, cB[3]);
                cA[4] = fma2(dA, w45.x, cA[4]); cB[4] = fma2(dB, w45.x, cB[4]);
                cA[5] = fma2(dA, w45.y, cA[5]); cB[5] = fma2(dB, w45.y, cB[5]);
                cA[6] = fma2(dA, w6,    cA[6]); cB[6] = fma2(dB, w6,    cB[6]);
            }
        }
#pragma unroll
        for (int p = 0; p < 7; p++) {
            sbA[p] = lif2(mbA[p], sbA[p], add2(cA[p], b24[p]));
            sbB[p] = lif2(mbB[p], sbB[p], add2(cB[p], b24[p]));
        }

        // branch spike stores (divergent, small)
        if (h == 0) {
            float f0, f1, f2, f3, f4, f5, f6, f7;
            float* p = p_sch + ((size_t)t * B + bA) * 8;   // 32B aligned
            unpack2(sbA[0], f0, f1); unpack2(sbA[1], f2, f3);
            unpack2(sbA[2], f4, f5); unpack2(sbA[3], f6, f7);
            __stcs((float4*)p,     make_float4(f0, f1, f2, f3));
            __stcs((float4*)p + 1, make_float4(f4, f5, f6, f7));
            unpack2(sbB[0], f0, f1); unpack2(sbB[1], f2, f3);
            unpack2(sbB[2], f4, f5); unpack2(sbB[3], f6, f7);
            __stcs((float4*)p + 2, make_float4(f0, f1, f2, f3));
            __stcs((float4*)p + 3, make_float4(f4, f5, f6, f7));
        } else {
            float* p = p_srh + ((size_t)t * B + bA) * 14;  // 8B aligned
#pragma unroll
            for (int k = 0; k < 7; k++) {
                float a0, a1;
                unpack2(sbA[k], a0, a1);
                __stcs((float2*)p + k, make_float2(a0, a1));
            }
            float* q = p + 14;
#pragma unroll
            for (int k = 0; k < 7; k++) {
                float b0, b1f;
                unpack2(sbB[k], b0, b1f);
                __stcs((float2*)q + k, make_float2(b0, b1f));
            }
        }

        // ---- out layer: 2 output-pairs x 2 batches <- 14 own spikes ----
        u64 oA0 = 0ull, oA1 = 0ull, oB0 = 0ull, oB1 = 0ull;
#pragma unroll
        for (int pp = 0; pp < 7; pp++) {
            float sa0, sa1, sb0, sb1;
            unpack2(sbA[pp], sa0, sa1);
            unpack2(sbB[pp], sb0, sb1);
#pragma unroll
            for (int half = 0; half < 2; half++) {
                const float sa = half ? sa1 : sa0;
                const float sb = half ? sb1 : sb0;
                const int i = 2 * pp + half;
                u64 dA = pack2(sa, sa);
                u64 dB = pack2(sb, sb);
                ulonglong2 wp = *(const ulonglong2*)(w5 + i * 4);
                oA0 = fma2(dA, wp.x, oA0); oA1 = fma2(dA, wp.y, oA1);
                oB0 = fma2(dB, wp.x, oB0); oB1 = fma2(dB, wp.y, oB1);
            }
        }
        soA0 = lif2(moA0, soA0, add2(oA0, b5[0]));
        soA1 = lif2(moA1, soA1, add2(oA1, b5[1]));
        soB0 = lif2(moB0, soB0, add2(oB0, b5[0]));
        soB1 = lif2(moB1, soB1, add2(oB1, b5[1]));

        if (h == 0) {
            float a0, a1, a2, pd, b0, b1f, b2;
            unpack2(moA0, a0, a1); unpack2(moA1, a2, pd);
            unpack2(moB0, b0, b1f); unpack2(moB1, b2, pd);
            float* p = p_mco + ((size_t)t * B + bA) * 3;   // 8B aligned
            __stcs((float2*)p,     make_float2(a0, a1));
            __stcs((float2*)p + 1, make_float2(a2, b0));
            __stcs((float2*)p + 2, make_float2(b1f, b2));
        } else {
            float rA, rB, pd;
            unpack2(moA0, rA, pd);
            unpack2(moB0, rB, pd);
            __stcs((float2*)(p_mro + (size_t)t * B + bA), make_float2(rA, rB));
        }
    }
}

extern "C" void kernel_launch(void* const* d_in, const int* in_sizes, int n_in,
                              void* d_out, int out_size) {
    const float* x   = (const float*)d_in[0];
    const float* Wsh = (const float*)d_in[1];
    const float* bsh = (const float*)d_in[2];
    const float* Wch = (const float*)d_in[3];
    const float* bch = (const float*)d_in[4];
    const float* Wco = (const float*)d_in[5];
    const float* bco = (const float*)d_in[6];
    const float* Wrh = (const float*)d_in[7];
    const float* brh = (const float*)d_in[8];
    const float* Wro = (const float*)d_in[9];
    const float* bro = (const float*)d_in[10];

    const int B = in_sizes[0] / (TT * NIN);
    const int blocks = (B + THREADS - 1) / THREADS;   // threads == B

    snn_kernel<<<blocks, THREADS>>>(x, Wsh, bsh, Wch, bch, Wco, bco,
                                    Wrh, brh, Wro, bro, (float*)d_out, B);
}